// round 11
// baseline (speedup 1.0000x reference)
#include <cuda_runtime.h>

#define C   32
#define HF  96
#define WF  192
#define DD  192
#define HOUT 384
#define WOUT 768
#define ND  48
#define CHW (HF*WF)
#define COST_ELEMS (DD*HF*WF)
#define TP  (WF + 16)          // padded t/it rows: 16 zero floats before idx 0

// ---- packed f32x2 helpers (sm_103a) ----------------------------------------
__device__ __forceinline__ unsigned long long pack2(float lo, float hi) {
    unsigned long long r;
    asm("mov.b64 %0, {%1, %2};" : "=l"(r) : "f"(lo), "f"(hi));
    return r;
}
__device__ __forceinline__ void fma2(unsigned long long& acc,
                                     unsigned long long a, unsigned long long b) {
    asm("fma.rn.f32x2 %0, %1, %2, %0;" : "+l"(acc) : "l"(a), "l"(b));
}
__device__ __forceinline__ float2 unpack2(unsigned long long v) {
    float lo, hi;
    asm("mov.b64 {%0, %1}, %2;" : "=f"(lo), "=f"(hi) : "l"(v));
    return make_float2(lo, hi);
}

// ---------------------------------------------------------------------------
// Kernel 1: cosine cost volume slice, normalization deferred to store time.
// Identical math to the proven R8 kernel; the d-oct set a block computes is
// parameterized: oct = oct_off + oct_mul_by*by + oct_mul_dq*dq, dq < oct_ndq.
//   costA: off=0, mul_by=2, mul_dq=1, ndq=2 -> octs 0..5  (d < 48, pred input)
//   costB: off=6, mul_by=1, mul_dq=3, ndq=6 -> octs 6..23 (d >= 48)
// Threads with dq >= ndq exit after the (block-wide) load/norm phases.
// ---------------------------------------------------------------------------
__global__ __launch_bounds__(768, 1) void cost_kernel(
    const float* __restrict__ ref, const float* __restrict__ tgt,
    float* __restrict__ out,
    int oct_off, int oct_mul_by, int oct_mul_dq, int oct_ndq)
{
    extern __shared__ float smbuf[];
    float (*r)[C][WF]  = reinterpret_cast<float (*)[C][WF]>(smbuf);
    float (*t)[C][TP]  = reinterpret_cast<float (*)[C][TP]>(smbuf + 2*C*WF);
    float* part_r      = smbuf + 2*C*WF + 2*C*TP;          // [384]
    float* part_t      = part_r + 2*WF;                    // [384]
    float (*ir)[WF]    = reinterpret_cast<float (*)[WF]>(part_t + 2*WF);
    float (*itp)[TP]   = reinterpret_cast<float (*)[TP]>(
                             reinterpret_cast<float*>(ir) + 2*WF);

    const int hp  = blockIdx.x;
    const int by  = blockIdx.y;
    const int tid = threadIdx.x;
    const int hrow0 = hp * 2;

    if (tid < 256) {
        int row = tid / 128;
        int c   = (tid / 4) % C;
        int q   = tid % 4;
        *reinterpret_cast<float4*>(&t[row][c][q*4]) = make_float4(0.f,0.f,0.f,0.f);
    } else if (tid < 264) {
        int idx = tid - 256;
        int row = idx / 4;
        int q   = idx % 4;
        *reinterpret_cast<float4*>(&itp[row][q*4]) = make_float4(0.f,0.f,0.f,0.f);
    }

    #pragma unroll
    for (int j = 0; j < 4; j++) {
        int k   = tid + j*768;
        int c   = k / 48;
        int kk  = k % 48;
        int row = c / C;
        int cc  = c % C;
        *reinterpret_cast<float4*>(&r[row][cc][kk*4]) =
            *reinterpret_cast<const float4*>(ref + cc*CHW + (hrow0+row)*WF + kk*4);
        *reinterpret_cast<float4*>(&t[row][cc][16 + kk*4]) =
            *reinterpret_cast<const float4*>(tgt + cc*CHW + (hrow0+row)*WF + kk*4);
    }
    __syncthreads();

    {
        int col  = tid % 384;
        int half = tid / 384;
        int row  = col / WF;
        int w    = col % WF;
        float sr = 0.f, st = 0.f;
        int cbase = half * 16;
        #pragma unroll
        for (int c = 0; c < 16; c++) {
            float a = r[row][cbase + c][w];      sr = fmaf(a, a, sr);
            float b = t[row][cbase + c][16 + w]; st = fmaf(b, b, st);
        }
        if (half) { part_r[col] = sr; part_t[col] = st; }
        __syncthreads();
        if (!half) {
            ir[row][w]       = rsqrtf(sr + part_r[col] + 1e-12f);
            itp[row][16 + w] = rsqrtf(st + part_t[col] + 1e-12f);
        }
    }
    __syncthreads();

    const int hr = (tid >= 384) ? 1 : 0;
    const int tm = tid - hr*384;
    const int wq = tm % 48;
    const int dq = tm / 48;
    if (dq >= oct_ndq) return;           // inactive d-oct slot for this launch
    const int w0 = wq * 4;
    const int d0 = 8 * (oct_off + oct_mul_by*by + oct_mul_dq*dq);
    const int h  = hrow0 + hr;

    unsigned long long axy0[8], azw0[8];
    #pragma unroll
    for (int i = 0; i < 8; i++) { axy0[i] = 0ULL; azw0[i] = 0ULL; }

    const int pb = 16 + w0 - d0 - 8;

    if (w0 - d0 >= 0) {
        for (int c = 0; c < C; c++) {
            float4 a  = *reinterpret_cast<const float4*>(&r[hr][c][w0]);
            float4 v0 = *reinterpret_cast<const float4*>(&t[hr][c][pb]);
            float4 v1 = *reinterpret_cast<const float4*>(&t[hr][c][pb + 4]);
            float4 v2 = *reinterpret_cast<const float4*>(&t[hr][c][pb + 8]);
            float e[12] = {v0.x, v0.y, v0.z, v0.w,
                           v1.x, v1.y, v1.z, v1.w,
                           v2.x, v2.y, v2.z, v2.w};
            unsigned long long pxy = pack2(a.x, a.y);
            unsigned long long pzw = pack2(a.z, a.w);
            #pragma unroll
            for (int j = 1; j <= 10; j++) {
                unsigned long long P = pack2(e[j], e[j+1]);
                if (j <= 8) fma2(axy0[8 - j], pxy, P);
                if (j >= 3) fma2(azw0[10 - j], pzw, P);
            }
        }
        float4 irq = *reinterpret_cast<const float4*>(&ir[hr][w0]);
        float4 s0 = *reinterpret_cast<const float4*>(&itp[hr][pb]);
        float4 s1 = *reinterpret_cast<const float4*>(&itp[hr][pb + 4]);
        float4 s2 = *reinterpret_cast<const float4*>(&itp[hr][pb + 8]);
        float e[12] = {s0.x, s0.y, s0.z, s0.w,
                       s1.x, s1.y, s1.z, s1.w,
                       s2.x, s2.y, s2.z, s2.w};
        #pragma unroll
        for (int i = 0; i < 8; i++) {
            float2 xy = unpack2(axy0[i]);
            float2 zw = unpack2(azw0[i]);
            float4 o;
            o.x = xy.x * irq.x * e[8  - i];
            o.y = xy.y * irq.y * e[9  - i];
            o.z = zw.x * irq.z * e[10 - i];
            o.w = zw.y * irq.w * e[11 - i];
            *reinterpret_cast<float4*>(&out[((d0 + i)*HF + h)*WF + w0]) = o;
        }
    } else {
        float4 z = make_float4(0.f, 0.f, 0.f, 0.f);
        #pragma unroll
        for (int i = 0; i < 8; i++)
            *reinterpret_cast<float4*>(&out[((d0 + i)*HF + h)*WF + w0]) = z;
    }
}

// ---------------------------------------------------------------------------
// Kernel 2: fused trilinear upsample + argmax + clamp(.,1).
// EXACT revert to the R7 version (measured 13.7us): direct 4-corner chunked
// streaming, explicit buffer alternation, x8-scaled candidate scan.
// cand(e) = 7*s[e] + max(s[e-1],s[e+1]); exact samples 8*s[0] (k=0) and
// 8*s[47] (k=190). First-occurrence ties preserved.
// ---------------------------------------------------------------------------
#define SSTR 52

__device__ __forceinline__ float bilin1(const float* __restrict__ c00,
                                        const float* __restrict__ c01,
                                        const float* __restrict__ c10,
                                        const float* __restrict__ c11,
                                        int d, float fw, float fh)
{
    float t0 = fmaf(fw, c01[d] - c00[d], c00[d]);
    float t1 = fmaf(fw, c11[d] - c10[d], c10[d]);
    return fmaf(fh, t1 - t0, t0);
}

__device__ __forceinline__ void chunk8(const float* __restrict__ c00,
                                       const float* __restrict__ c01,
                                       const float* __restrict__ c10,
                                       const float* __restrict__ c11,
                                       int dbase, float fw, float fh,
                                       float* __restrict__ s)
{
    #pragma unroll
    for (int half = 0; half < 2; half++) {
        float4 v00 = *reinterpret_cast<const float4*>(c00 + dbase + half*4);
        float4 v01 = *reinterpret_cast<const float4*>(c01 + dbase + half*4);
        float4 v10 = *reinterpret_cast<const float4*>(c10 + dbase + half*4);
        float4 v11 = *reinterpret_cast<const float4*>(c11 + dbase + half*4);
        float t0, t1;
        t0 = fmaf(fw, v01.x - v00.x, v00.x);
        t1 = fmaf(fw, v11.x - v10.x, v10.x);
        s[half*4+0] = fmaf(fh, t1 - t0, t0);
        t0 = fmaf(fw, v01.y - v00.y, v00.y);
        t1 = fmaf(fw, v11.y - v10.y, v10.y);
        s[half*4+1] = fmaf(fh, t1 - t0, t0);
        t0 = fmaf(fw, v01.z - v00.z, v00.z);
        t1 = fmaf(fw, v11.z - v10.z, v10.z);
        s[half*4+2] = fmaf(fh, t1 - t0, t0);
        t0 = fmaf(fw, v01.w - v00.w, v00.w);
        t1 = fmaf(fw, v11.w - v10.w, v10.w);
        s[half*4+3] = fmaf(fh, t1 - t0, t0);
    }
}

__device__ __forceinline__ void scan_head(const float* __restrict__ s,
                                          float& best, int& bestE)
{
    #pragma unroll
    for (int e = 0; e < 7; e++) {
        float nb = (e == 0) ? s[1] : fmaxf(s[e-1], s[e+1]);
        float cand = fmaf(7.0f, s[e], nb);
        if (cand > best) { best = cand; bestE = e; }
    }
}

__device__ __forceinline__ void scan_mid(const float* __restrict__ p,
                                         const float* __restrict__ c,
                                         int qb, float& best, int& bestE)
{
    {   float nb = fmaxf(p[6], c[0]);
        float cand = fmaf(7.0f, p[7], nb);
        if (cand > best) { best = cand; bestE = qb - 1; } }
    {   float nb = fmaxf(p[7], c[1]);
        float cand = fmaf(7.0f, c[0], nb);
        if (cand > best) { best = cand; bestE = qb; } }
    #pragma unroll
    for (int j = 1; j < 7; j++) {
        float nb = fmaxf(c[j-1], c[j+1]);
        float cand = fmaf(7.0f, c[j], nb);
        if (cand > best) { best = cand; bestE = qb + j; }
    }
}

__global__ __launch_bounds__(256) void pred_kernel(
    const float* __restrict__ cost, float* __restrict__ pred)
{
    __shared__ float sc[4][10][SSTR];
    const int tx = threadIdx.x, ty = threadIdx.y;
    const int tid = ty*32 + tx;
    const int hb = 2*(int)blockIdx.y - 1;
    const int wb = 8*(int)blockIdx.x - 1;

    #pragma unroll
    for (int it = 0; it < 8; it++) {
        int i = tid + it * 256;
        if (i < 4*10*ND) {
            int wc = i % 10;
            int hr = (i / 10) % 4;
            int d  = i / 40;
            int hh = min(max(hb + hr, 0), HF - 1);
            int ww = min(max(wb + wc, 0), WF - 1);
            sc[hr][wc][d] = cost[(d*HF + hh)*WF + ww];
        }
    }
    __syncthreads();

    const int wo = blockIdx.x*32 + tx;
    const int ho = blockIdx.y*8 + ty;

    float xh = fminf(fmaxf(0.25f*(float)ho - 0.375f, 0.f), (float)(HF - 1));
    int   h0 = min((int)xh, HF - 2);
    float fh = xh - (float)h0;
    float xw = fminf(fmaxf(0.25f*(float)wo - 0.375f, 0.f), (float)(WF - 1));
    int   w0 = min((int)xw, WF - 2);
    float fw = xw - (float)w0;

    const int lh = h0 - hb;
    const int lw = w0 - wb;
    const float* c00 = &sc[lh][lw][0];
    const float* c01 = &sc[lh][lw+1][0];
    const float* c10 = &sc[lh+1][lw][0];
    const float* c11 = &sc[lh+1][lw+1][0];

    float sA[8], sB[8];
    float best;
    int bestE = -1;                      // -1 => k = 0

    chunk8(c00, c01, c10, c11, 0, fw, fh, sA);
    best = 8.0f * sA[0];                 // exact sample s[0] (scaled)
    scan_head(sA, best, bestE);

    chunk8(c00, c01, c10, c11,  8, fw, fh, sB); scan_mid(sA, sB,  8, best, bestE);
    chunk8(c00, c01, c10, c11, 16, fw, fh, sA); scan_mid(sB, sA, 16, best, bestE);
    chunk8(c00, c01, c10, c11, 24, fw, fh, sB); scan_mid(sA, sB, 24, best, bestE);
    chunk8(c00, c01, c10, c11, 32, fw, fh, sA); scan_mid(sB, sA, 32, best, bestE);
    chunk8(c00, c01, c10, c11, 40, fw, fh, sB); scan_mid(sA, sB, 40, best, bestE);

    {   // e = 47
        float nb = sB[6];
        float cand = fmaf(7.0f, sB[7], nb);
        if (cand > best) { best = cand; bestE = 47; }
    }
    float s47 = sB[7];

    int k;
    if (8.0f * s47 > best) {
        k = 4*(ND-1) + 2;                   // 190: exact sample s[47]
    } else if (bestE < 0) {
        k = 0;
    } else {
        float smL = -3.0e38f, smR = -3.0e38f;
        if (bestE > 0)      smL = bilin1(c00, c01, c10, c11, bestE - 1, fw, fh);
        if (bestE < ND - 1) smR = bilin1(c00, c01, c10, c11, bestE + 1, fw, fh);
        k = 4*bestE + 1 + ((smR > smL) ? 1 : 0);   // tie -> left (smaller k)
    }
    k = max(k, 1);
    pred[ho*WOUT + wo] = (float)k;
}

// ---------------------------------------------------------------------------
// Launch: fork costB (d>=48, unused by pred) onto a side stream so it runs
// concurrently with pred, which only needs costA (d<48). Stream/events are
// created once in a static initializer (no device allocation); the fork/join
// uses the standard event pattern, which is CUDA-graph-capturable.
// ---------------------------------------------------------------------------
static cudaStream_t g_s2;
static cudaEvent_t  g_e0, g_e1;
static struct _StreamInit {
    _StreamInit() {
        cudaStreamCreateWithFlags(&g_s2, cudaStreamNonBlocking);
        cudaEventCreateWithFlags(&g_e0, cudaEventDisableTiming);
        cudaEventCreateWithFlags(&g_e1, cudaEventDisableTiming);
    }
} g_stream_init;

extern "C" void kernel_launch(void* const* d_in, const int* in_sizes, int n_in,
                              void* d_out, int out_size)
{
    const float* left  = (const float*)d_in[0];
    const float* right = (const float*)d_in[1];
    float* out = (float*)d_out;

    const int smem_bytes =
        (2*C*WF + 2*C*TP + 2*WF + 2*WF + 2*WF + 2*TP) * (int)sizeof(float);
    cudaFuncSetAttribute(cost_kernel,
                         cudaFuncAttributeMaxDynamicSharedMemorySize, smem_bytes);

    dim3 gc(HF/2, 3), bc(768);

    // fork: side stream branches off the main stream at entry
    cudaEventRecord(g_e0, 0);
    cudaStreamWaitEvent(g_s2, g_e0, 0);

    // costB: octs 6..23 (d in [48,192)) -> side stream, independent of pred
    cost_kernel<<<gc, bc, smem_bytes, g_s2>>>(left, right, out, 6, 1, 3, 6);

    // costA: octs 0..5 (d in [0,48)) -> main stream, feeds pred
    cost_kernel<<<gc, bc, smem_bytes>>>(left, right, out, 0, 2, 1, 2);

    dim3 g2(WOUT/32, HOUT/8), b2(32, 8);
    pred_kernel<<<g2, b2>>>(out, out + COST_ELEMS);

    // join: main stream waits for costB before returning
    cudaEventRecord(g_e1, g_s2);
    cudaStreamWaitEvent(0, g_e1, 0);
}

// round 12
// speedup vs baseline: 1.1346x; 1.1346x over previous
#include <cuda_runtime.h>

#define C   32
#define HF  96
#define WF  192
#define DD  192
#define HOUT 384
#define WOUT 768
#define ND  48
#define CHW (HF*WF)
#define COST_ELEMS (DD*HF*WF)
#define TP  (WF + 16)          // padded t/it rows: 16 zero floats before idx 0

// ---- packed f32x2 helpers (sm_103a) ----------------------------------------
__device__ __forceinline__ unsigned long long pack2(float lo, float hi) {
    unsigned long long r;
    asm("mov.b64 %0, {%1, %2};" : "=l"(r) : "f"(lo), "f"(hi));
    return r;
}
__device__ __forceinline__ void fma2(unsigned long long& acc,
                                     unsigned long long a, unsigned long long b) {
    asm("fma.rn.f32x2 %0, %1, %2, %0;" : "+l"(acc) : "l"(a), "l"(b));
}
__device__ __forceinline__ float2 unpack2(unsigned long long v) {
    float lo, hi;
    asm("mov.b64 {%0, %1}, %2;" : "=f"(lo), "=f"(hi) : "l"(v));
    return make_float2(lo, hi);
}

// ---------------------------------------------------------------------------
// Kernel 1: cosine cost volume, normalization deferred to store time.
// EXACT R8 version (measured ~8.7us). ONE WAVE: grid (48 h-pairs, 3),
// 768 threads, ~106KB dynamic smem. smem holds UNNORMALIZED r,t rows;
// per-pixel inverse norms ir/it computed by all 24 warps (split-c partials).
// Main loop: one 4w x 8d tile per thread, LDS.128 operands, fma.rn.f32x2
// accumulation. Store applies out = acc * ir[w] * it[w-d]; zero-padded t AND
// it keep exact zeros for w < d with a single branch-free code path.
// ---------------------------------------------------------------------------
__global__ __launch_bounds__(768, 1) void cost_kernel(
    const float* __restrict__ ref, const float* __restrict__ tgt,
    float* __restrict__ out)
{
    extern __shared__ float smbuf[];
    float (*r)[C][WF]  = reinterpret_cast<float (*)[C][WF]>(smbuf);
    float (*t)[C][TP]  = reinterpret_cast<float (*)[C][TP]>(smbuf + 2*C*WF);
    float* part_r      = smbuf + 2*C*WF + 2*C*TP;          // [384]
    float* part_t      = part_r + 2*WF;                    // [384]
    float (*ir)[WF]    = reinterpret_cast<float (*)[WF]>(part_t + 2*WF);
    float (*itp)[TP]   = reinterpret_cast<float (*)[TP]>(
                             reinterpret_cast<float*>(ir) + 2*WF);

    const int hp  = blockIdx.x;
    const int by  = blockIdx.y;
    const int tid = threadIdx.x;
    const int hrow0 = hp * 2;

    if (tid < 256) {
        int row = tid / 128;
        int c   = (tid / 4) % C;
        int q   = tid % 4;
        *reinterpret_cast<float4*>(&t[row][c][q*4]) = make_float4(0.f,0.f,0.f,0.f);
    } else if (tid < 264) {
        int idx = tid - 256;
        int row = idx / 4;
        int q   = idx % 4;
        *reinterpret_cast<float4*>(&itp[row][q*4]) = make_float4(0.f,0.f,0.f,0.f);
    }

    #pragma unroll
    for (int j = 0; j < 4; j++) {
        int k   = tid + j*768;
        int c   = k / 48;
        int kk  = k % 48;
        int row = c / C;
        int cc  = c % C;
        *reinterpret_cast<float4*>(&r[row][cc][kk*4]) =
            *reinterpret_cast<const float4*>(ref + cc*CHW + (hrow0+row)*WF + kk*4);
        *reinterpret_cast<float4*>(&t[row][cc][16 + kk*4]) =
            *reinterpret_cast<const float4*>(tgt + cc*CHW + (hrow0+row)*WF + kk*4);
    }
    __syncthreads();

    {
        int col  = tid % 384;
        int half = tid / 384;
        int row  = col / WF;
        int w    = col % WF;
        float sr = 0.f, st = 0.f;
        int cbase = half * 16;
        #pragma unroll
        for (int c = 0; c < 16; c++) {
            float a = r[row][cbase + c][w];      sr = fmaf(a, a, sr);
            float b = t[row][cbase + c][16 + w]; st = fmaf(b, b, st);
        }
        if (half) { part_r[col] = sr; part_t[col] = st; }
        __syncthreads();
        if (!half) {
            ir[row][w]       = rsqrtf(sr + part_r[col] + 1e-12f);
            itp[row][16 + w] = rsqrtf(st + part_t[col] + 1e-12f);
        }
    }
    __syncthreads();

    const int hr = (tid >= 384) ? 1 : 0;
    const int tm = tid - hr*384;
    const int wq = tm % 48;
    const int dq = tm / 48;
    const int w0 = wq * 4;
    const int d0 = 8 * (3*dq + by);      // interleaved d-oct (triangle balance)
    const int h  = hrow0 + hr;

    unsigned long long axy0[8], azw0[8];
    #pragma unroll
    for (int i = 0; i < 8; i++) { axy0[i] = 0ULL; azw0[i] = 0ULL; }

    const int pb = 16 + w0 - d0 - 8;

    if (w0 - d0 >= 0) {
        for (int c = 0; c < C; c++) {
            float4 a  = *reinterpret_cast<const float4*>(&r[hr][c][w0]);
            float4 v0 = *reinterpret_cast<const float4*>(&t[hr][c][pb]);
            float4 v1 = *reinterpret_cast<const float4*>(&t[hr][c][pb + 4]);
            float4 v2 = *reinterpret_cast<const float4*>(&t[hr][c][pb + 8]);
            float e[12] = {v0.x, v0.y, v0.z, v0.w,
                           v1.x, v1.y, v1.z, v1.w,
                           v2.x, v2.y, v2.z, v2.w};
            unsigned long long pxy = pack2(a.x, a.y);
            unsigned long long pzw = pack2(a.z, a.w);
            #pragma unroll
            for (int j = 1; j <= 10; j++) {
                unsigned long long P = pack2(e[j], e[j+1]);
                if (j <= 8) fma2(axy0[8 - j], pxy, P);
                if (j >= 3) fma2(azw0[10 - j], pzw, P);
            }
        }
        float4 irq = *reinterpret_cast<const float4*>(&ir[hr][w0]);
        float4 s0 = *reinterpret_cast<const float4*>(&itp[hr][pb]);
        float4 s1 = *reinterpret_cast<const float4*>(&itp[hr][pb + 4]);
        float4 s2 = *reinterpret_cast<const float4*>(&itp[hr][pb + 8]);
        float e[12] = {s0.x, s0.y, s0.z, s0.w,
                       s1.x, s1.y, s1.z, s1.w,
                       s2.x, s2.y, s2.z, s2.w};
        #pragma unroll
        for (int i = 0; i < 8; i++) {
            float2 xy = unpack2(axy0[i]);
            float2 zw = unpack2(azw0[i]);
            float4 o;
            o.x = xy.x * irq.x * e[8  - i];
            o.y = xy.y * irq.y * e[9  - i];
            o.z = zw.x * irq.z * e[10 - i];
            o.w = zw.y * irq.w * e[11 - i];
            *reinterpret_cast<float4*>(&out[((d0 + i)*HF + h)*WF + w0]) = o;
        }
    } else {
        float4 z = make_float4(0.f, 0.f, 0.f, 0.f);
        #pragma unroll
        for (int i = 0; i < 8; i++)
            *reinterpret_cast<float4*>(&out[((d0 + i)*HF + h)*WF + w0]) = z;
    }
}

// ---------------------------------------------------------------------------
// Kernel 2: fused trilinear upsample + argmax + clamp(.,1).
// EXACT R7 version (measured 13.7us): direct 4-corner chunked streaming,
// explicit buffer alternation, x8-scaled candidate scan (exact, order-
// preserving): cand(e) = 7*s[e] + max(s[e-1],s[e+1]); exact samples
// 8*s[0] (k=0) and 8*s[47] (k=190). First-occurrence ties preserved.
// ---------------------------------------------------------------------------
#define SSTR 52

__device__ __forceinline__ float bilin1(const float* __restrict__ c00,
                                        const float* __restrict__ c01,
                                        const float* __restrict__ c10,
                                        const float* __restrict__ c11,
                                        int d, float fw, float fh)
{
    float t0 = fmaf(fw, c01[d] - c00[d], c00[d]);
    float t1 = fmaf(fw, c11[d] - c10[d], c10[d]);
    return fmaf(fh, t1 - t0, t0);
}

__device__ __forceinline__ void chunk8(const float* __restrict__ c00,
                                       const float* __restrict__ c01,
                                       const float* __restrict__ c10,
                                       const float* __restrict__ c11,
                                       int dbase, float fw, float fh,
                                       float* __restrict__ s)
{
    #pragma unroll
    for (int half = 0; half < 2; half++) {
        float4 v00 = *reinterpret_cast<const float4*>(c00 + dbase + half*4);
        float4 v01 = *reinterpret_cast<const float4*>(c01 + dbase + half*4);
        float4 v10 = *reinterpret_cast<const float4*>(c10 + dbase + half*4);
        float4 v11 = *reinterpret_cast<const float4*>(c11 + dbase + half*4);
        float t0, t1;
        t0 = fmaf(fw, v01.x - v00.x, v00.x);
        t1 = fmaf(fw, v11.x - v10.x, v10.x);
        s[half*4+0] = fmaf(fh, t1 - t0, t0);
        t0 = fmaf(fw, v01.y - v00.y, v00.y);
        t1 = fmaf(fw, v11.y - v10.y, v10.y);
        s[half*4+1] = fmaf(fh, t1 - t0, t0);
        t0 = fmaf(fw, v01.z - v00.z, v00.z);
        t1 = fmaf(fw, v11.z - v10.z, v10.z);
        s[half*4+2] = fmaf(fh, t1 - t0, t0);
        t0 = fmaf(fw, v01.w - v00.w, v00.w);
        t1 = fmaf(fw, v11.w - v10.w, v10.w);
        s[half*4+3] = fmaf(fh, t1 - t0, t0);
    }
}

__device__ __forceinline__ void scan_head(const float* __restrict__ s,
                                          float& best, int& bestE)
{
    #pragma unroll
    for (int e = 0; e < 7; e++) {
        float nb = (e == 0) ? s[1] : fmaxf(s[e-1], s[e+1]);
        float cand = fmaf(7.0f, s[e], nb);
        if (cand > best) { best = cand; bestE = e; }
    }
}

__device__ __forceinline__ void scan_mid(const float* __restrict__ p,
                                         const float* __restrict__ c,
                                         int qb, float& best, int& bestE)
{
    {   float nb = fmaxf(p[6], c[0]);
        float cand = fmaf(7.0f, p[7], nb);
        if (cand > best) { best = cand; bestE = qb - 1; } }
    {   float nb = fmaxf(p[7], c[1]);
        float cand = fmaf(7.0f, c[0], nb);
        if (cand > best) { best = cand; bestE = qb; } }
    #pragma unroll
    for (int j = 1; j < 7; j++) {
        float nb = fmaxf(c[j-1], c[j+1]);
        float cand = fmaf(7.0f, c[j], nb);
        if (cand > best) { best = cand; bestE = qb + j; }
    }
}

__global__ __launch_bounds__(256) void pred_kernel(
    const float* __restrict__ cost, float* __restrict__ pred)
{
    __shared__ float sc[4][10][SSTR];
    const int tx = threadIdx.x, ty = threadIdx.y;
    const int tid = ty*32 + tx;
    const int hb = 2*(int)blockIdx.y - 1;
    const int wb = 8*(int)blockIdx.x - 1;

    #pragma unroll
    for (int it = 0; it < 8; it++) {
        int i = tid + it * 256;
        if (i < 4*10*ND) {
            int wc = i % 10;
            int hr = (i / 10) % 4;
            int d  = i / 40;
            int hh = min(max(hb + hr, 0), HF - 1);
            int ww = min(max(wb + wc, 0), WF - 1);
            sc[hr][wc][d] = cost[(d*HF + hh)*WF + ww];
        }
    }
    __syncthreads();

    const int wo = blockIdx.x*32 + tx;
    const int ho = blockIdx.y*8 + ty;

    float xh = fminf(fmaxf(0.25f*(float)ho - 0.375f, 0.f), (float)(HF - 1));
    int   h0 = min((int)xh, HF - 2);
    float fh = xh - (float)h0;
    float xw = fminf(fmaxf(0.25f*(float)wo - 0.375f, 0.f), (float)(WF - 1));
    int   w0 = min((int)xw, WF - 2);
    float fw = xw - (float)w0;

    const int lh = h0 - hb;
    const int lw = w0 - wb;
    const float* c00 = &sc[lh][lw][0];
    const float* c01 = &sc[lh][lw+1][0];
    const float* c10 = &sc[lh+1][lw][0];
    const float* c11 = &sc[lh+1][lw+1][0];

    float sA[8], sB[8];
    float best;
    int bestE = -1;                      // -1 => k = 0

    chunk8(c00, c01, c10, c11, 0, fw, fh, sA);
    best = 8.0f * sA[0];                 // exact sample s[0] (scaled)
    scan_head(sA, best, bestE);

    chunk8(c00, c01, c10, c11,  8, fw, fh, sB); scan_mid(sA, sB,  8, best, bestE);
    chunk8(c00, c01, c10, c11, 16, fw, fh, sA); scan_mid(sB, sA, 16, best, bestE);
    chunk8(c00, c01, c10, c11, 24, fw, fh, sB); scan_mid(sA, sB, 24, best, bestE);
    chunk8(c00, c01, c10, c11, 32, fw, fh, sA); scan_mid(sB, sA, 32, best, bestE);
    chunk8(c00, c01, c10, c11, 40, fw, fh, sB); scan_mid(sA, sB, 40, best, bestE);

    {   // e = 47
        float nb = sB[6];
        float cand = fmaf(7.0f, sB[7], nb);
        if (cand > best) { best = cand; bestE = 47; }
    }
    float s47 = sB[7];

    int k;
    if (8.0f * s47 > best) {
        k = 4*(ND-1) + 2;                   // 190: exact sample s[47]
    } else if (bestE < 0) {
        k = 0;
    } else {
        float smL = -3.0e38f, smR = -3.0e38f;
        if (bestE > 0)      smL = bilin1(c00, c01, c10, c11, bestE - 1, fw, fh);
        if (bestE < ND - 1) smR = bilin1(c00, c01, c10, c11, bestE + 1, fw, fh);
        k = 4*bestE + 1 + ((smR > smL) ? 1 : 0);   // tie -> left (smaller k)
    }
    k = max(k, 1);
    pred[ho*WOUT + wo] = (float)k;
}

// ---------------------------------------------------------------------------
extern "C" void kernel_launch(void* const* d_in, const int* in_sizes, int n_in,
                              void* d_out, int out_size)
{
    const float* left  = (const float*)d_in[0];
    const float* right = (const float*)d_in[1];
    float* out = (float*)d_out;

    const int smem_bytes =
        (2*C*WF + 2*C*TP + 2*WF + 2*WF + 2*WF + 2*TP) * (int)sizeof(float);
    cudaFuncSetAttribute(cost_kernel,
                         cudaFuncAttributeMaxDynamicSharedMemorySize, smem_bytes);

    dim3 g1(HF/2, 3), b1(768);
    cost_kernel<<<g1, b1, smem_bytes>>>(left, right, out);

    dim3 g2(WOUT/32, HOUT/8), b2(32, 8);
    pred_kernel<<<g2, b2>>>(out, out + COST_ELEMS);
}

// round 13
// speedup vs baseline: 1.2273x; 1.0817x over previous
#include <cuda_runtime.h>

#define C   32
#define HF  96
#define WF  192
#define DD  192
#define HOUT 384
#define WOUT 768
#define ND  48
#define CHW (HF*WF)
#define COST_ELEMS (DD*HF*WF)
#define TP  (WF + 16)          // padded t/it rows: 16 zero floats before idx 0

// ---- packed f32x2 helpers (sm_103a) ----------------------------------------
__device__ __forceinline__ unsigned long long pack2(float lo, float hi) {
    unsigned long long r;
    asm("mov.b64 %0, {%1, %2};" : "=l"(r) : "f"(lo), "f"(hi));
    return r;
}
__device__ __forceinline__ void fma2(unsigned long long& acc,
                                     unsigned long long a, unsigned long long b) {
    asm("fma.rn.f32x2 %0, %1, %2, %0;" : "+l"(acc) : "l"(a), "l"(b));
}
__device__ __forceinline__ float2 unpack2(unsigned long long v) {
    float lo, hi;
    asm("mov.b64 {%0, %1}, %2;" : "=f"(lo), "=f"(hi) : "l"(v));
    return make_float2(lo, hi);
}

// ---------------------------------------------------------------------------
// Kernel 1: cosine cost volume, normalization deferred to store time.
// NEW SHAPE: one h-ROW per block (54KB smem) -> 2 co-resident blocks/SM,
// 48 warps/SM; one block's load/norm prologue overlaps the other's compute.
// Grid (96 h, 3 by), 384 threads; each thread computes one 4w x 8d tile
// (48 wq x 8 dq = 384), d-oct = 3*dq + by (triangle-balanced interleave).
// Zero-padded t and it rows keep exact zeros for w < d, single code path.
// out[d,h,w] = (sum_c r[c,w]*t[c,w-d]) * ir[w] * it[w-d].
// ---------------------------------------------------------------------------
__global__ __launch_bounds__(384, 2) void cost_kernel(
    const float* __restrict__ ref, const float* __restrict__ tgt,
    float* __restrict__ out)
{
    extern __shared__ float smbuf[];
    float (*r)[WF]  = reinterpret_cast<float (*)[WF]>(smbuf);            // [C][WF]
    float (*t)[TP]  = reinterpret_cast<float (*)[TP]>(smbuf + C*WF);     // [C][TP]
    float* part_r   = smbuf + C*WF + C*TP;                               // [192]
    float* part_t   = part_r + WF;                                       // [192]
    float* ir       = part_t + WF;                                       // [WF]
    float* itp      = ir + WF;                                           // [TP]

    const int h   = blockIdx.x;          // h-row 0..95
    const int by  = blockIdx.y;          // 0..2
    const int tid = threadIdx.x;         // 0..383

    // zero pads: t pad = C*16 floats (128 f4), itp pad = 16 floats (4 f4)
    if (tid < 128) {
        int c = tid / 4;
        int q = tid % 4;
        *reinterpret_cast<float4*>(&t[c][q*4]) = make_float4(0.f,0.f,0.f,0.f);
    } else if (tid < 132) {
        int q = tid - 128;
        *reinterpret_cast<float4*>(&itp[q*4]) = make_float4(0.f,0.f,0.f,0.f);
    }

    // vectorized loads: 1536 float4 per tensor (32 c x 48 quads)
    #pragma unroll
    for (int j = 0; j < 4; j++) {
        int k  = tid + j*384;            // 0..1535
        int c  = k / 48;
        int kk = k % 48;
        *reinterpret_cast<float4*>(&r[c][kk*4]) =
            *reinterpret_cast<const float4*>(ref + c*CHW + h*WF + kk*4);
        *reinterpret_cast<float4*>(&t[c][16 + kk*4]) =
            *reinterpret_cast<const float4*>(tgt + c*CHW + h*WF + kk*4);
    }
    __syncthreads();

    // inverse norms: 192 columns x 2 half-c partials (all 12 warps active)
    {
        int w    = tid % WF;
        int half = tid / WF;             // 0 or 1
        float sr = 0.f, st = 0.f;
        int cbase = half * 16;
        #pragma unroll
        for (int c = 0; c < 16; c++) {
            float a = r[cbase + c][w];      sr = fmaf(a, a, sr);
            float b = t[cbase + c][16 + w]; st = fmaf(b, b, st);
        }
        if (half) { part_r[w] = sr; part_t[w] = st; }
        __syncthreads();
        if (!half) {
            ir[w]       = rsqrtf(sr + part_r[w] + 1e-12f);
            itp[16 + w] = rsqrtf(st + part_t[w] + 1e-12f);
        }
    }
    __syncthreads();

    // one 4w x 8d tile per thread: 48 wq x 8 dq = 384 tiles
    const int wq = tid % 48;
    const int dq = tid / 48;             // 0..7
    const int w0 = wq * 4;
    const int d0 = 8 * (3*dq + by);      // octs 0..23

    unsigned long long axy0[8], azw0[8]; // (x,y)/(z,w) packed accs per i
    #pragma unroll
    for (int i = 0; i < 8; i++) { axy0[i] = 0ULL; azw0[i] = 0ULL; }

    const int pb = 16 + w0 - d0 - 8;     // padded window base (mult of 4)

    if (w0 - d0 >= 0) {
        for (int c = 0; c < C; c++) {
            float4 a  = *reinterpret_cast<const float4*>(&r[c][w0]);
            float4 v0 = *reinterpret_cast<const float4*>(&t[c][pb]);
            float4 v1 = *reinterpret_cast<const float4*>(&t[c][pb + 4]);
            float4 v2 = *reinterpret_cast<const float4*>(&t[c][pb + 8]);
            float e[12] = {v0.x, v0.y, v0.z, v0.w,
                           v1.x, v1.y, v1.z, v1.w,
                           v2.x, v2.y, v2.z, v2.w};
            unsigned long long pxy = pack2(a.x, a.y);
            unsigned long long pzw = pack2(a.z, a.w);
            #pragma unroll
            for (int j = 1; j <= 10; j++) {
                unsigned long long P = pack2(e[j], e[j+1]);
                if (j <= 8) fma2(axy0[8 - j], pxy, P);
                if (j >= 3) fma2(azw0[10 - j], pzw, P);
            }
        }
        float4 irq = *reinterpret_cast<const float4*>(&ir[w0]);
        float4 s0 = *reinterpret_cast<const float4*>(&itp[pb]);
        float4 s1 = *reinterpret_cast<const float4*>(&itp[pb + 4]);
        float4 s2 = *reinterpret_cast<const float4*>(&itp[pb + 8]);
        float e[12] = {s0.x, s0.y, s0.z, s0.w,
                       s1.x, s1.y, s1.z, s1.w,
                       s2.x, s2.y, s2.z, s2.w};
        #pragma unroll
        for (int i = 0; i < 8; i++) {
            float2 xy = unpack2(axy0[i]);
            float2 zw = unpack2(azw0[i]);
            float4 o;
            o.x = xy.x * irq.x * e[8  - i];
            o.y = xy.y * irq.y * e[9  - i];
            o.z = zw.x * irq.z * e[10 - i];
            o.w = zw.y * irq.w * e[11 - i];
            *reinterpret_cast<float4*>(&out[((d0 + i)*HF + h)*WF + w0]) = o;
        }
    } else {
        float4 z = make_float4(0.f, 0.f, 0.f, 0.f);
        #pragma unroll
        for (int i = 0; i < 8; i++)
            *reinterpret_cast<float4*>(&out[((d0 + i)*HF + h)*WF + w0]) = z;
    }
}

// ---------------------------------------------------------------------------
// Kernel 2: fused trilinear upsample + argmax + clamp(.,1).
// EXACT R7/R12 version: direct 4-corner chunked streaming, explicit buffer
// alternation, x8-scaled candidate scan (exact, order-preserving):
// cand(e) = 7*s[e] + max(s[e-1],s[e+1]); exact samples 8*s[0] (k=0) and
// 8*s[47] (k=190). First-occurrence ties preserved.
// ---------------------------------------------------------------------------
#define SSTR 52

__device__ __forceinline__ float bilin1(const float* __restrict__ c00,
                                        const float* __restrict__ c01,
                                        const float* __restrict__ c10,
                                        const float* __restrict__ c11,
                                        int d, float fw, float fh)
{
    float t0 = fmaf(fw, c01[d] - c00[d], c00[d]);
    float t1 = fmaf(fw, c11[d] - c10[d], c10[d]);
    return fmaf(fh, t1 - t0, t0);
}

__device__ __forceinline__ void chunk8(const float* __restrict__ c00,
                                       const float* __restrict__ c01,
                                       const float* __restrict__ c10,
                                       const float* __restrict__ c11,
                                       int dbase, float fw, float fh,
                                       float* __restrict__ s)
{
    #pragma unroll
    for (int half = 0; half < 2; half++) {
        float4 v00 = *reinterpret_cast<const float4*>(c00 + dbase + half*4);
        float4 v01 = *reinterpret_cast<const float4*>(c01 + dbase + half*4);
        float4 v10 = *reinterpret_cast<const float4*>(c10 + dbase + half*4);
        float4 v11 = *reinterpret_cast<const float4*>(c11 + dbase + half*4);
        float t0, t1;
        t0 = fmaf(fw, v01.x - v00.x, v00.x);
        t1 = fmaf(fw, v11.x - v10.x, v10.x);
        s[half*4+0] = fmaf(fh, t1 - t0, t0);
        t0 = fmaf(fw, v01.y - v00.y, v00.y);
        t1 = fmaf(fw, v11.y - v10.y, v10.y);
        s[half*4+1] = fmaf(fh, t1 - t0, t0);
        t0 = fmaf(fw, v01.z - v00.z, v00.z);
        t1 = fmaf(fw, v11.z - v10.z, v10.z);
        s[half*4+2] = fmaf(fh, t1 - t0, t0);
        t0 = fmaf(fw, v01.w - v00.w, v00.w);
        t1 = fmaf(fw, v11.w - v10.w, v10.w);
        s[half*4+3] = fmaf(fh, t1 - t0, t0);
    }
}

__device__ __forceinline__ void scan_head(const float* __restrict__ s,
                                          float& best, int& bestE)
{
    #pragma unroll
    for (int e = 0; e < 7; e++) {
        float nb = (e == 0) ? s[1] : fmaxf(s[e-1], s[e+1]);
        float cand = fmaf(7.0f, s[e], nb);
        if (cand > best) { best = cand; bestE = e; }
    }
}

__device__ __forceinline__ void scan_mid(const float* __restrict__ p,
                                         const float* __restrict__ c,
                                         int qb, float& best, int& bestE)
{
    {   float nb = fmaxf(p[6], c[0]);
        float cand = fmaf(7.0f, p[7], nb);
        if (cand > best) { best = cand; bestE = qb - 1; } }
    {   float nb = fmaxf(p[7], c[1]);
        float cand = fmaf(7.0f, c[0], nb);
        if (cand > best) { best = cand; bestE = qb; } }
    #pragma unroll
    for (int j = 1; j < 7; j++) {
        float nb = fmaxf(c[j-1], c[j+1]);
        float cand = fmaf(7.0f, c[j], nb);
        if (cand > best) { best = cand; bestE = qb + j; }
    }
}

__global__ __launch_bounds__(256) void pred_kernel(
    const float* __restrict__ cost, float* __restrict__ pred)
{
    __shared__ float sc[4][10][SSTR];
    const int tx = threadIdx.x, ty = threadIdx.y;
    const int tid = ty*32 + tx;
    const int hb = 2*(int)blockIdx.y - 1;
    const int wb = 8*(int)blockIdx.x - 1;

    #pragma unroll
    for (int it = 0; it < 8; it++) {
        int i = tid + it * 256;
        if (i < 4*10*ND) {
            int wc = i % 10;
            int hr = (i / 10) % 4;
            int d  = i / 40;
            int hh = min(max(hb + hr, 0), HF - 1);
            int ww = min(max(wb + wc, 0), WF - 1);
            sc[hr][wc][d] = cost[(d*HF + hh)*WF + ww];
        }
    }
    __syncthreads();

    const int wo = blockIdx.x*32 + tx;
    const int ho = blockIdx.y*8 + ty;

    float xh = fminf(fmaxf(0.25f*(float)ho - 0.375f, 0.f), (float)(HF - 1));
    int   h0 = min((int)xh, HF - 2);
    float fh = xh - (float)h0;
    float xw = fminf(fmaxf(0.25f*(float)wo - 0.375f, 0.f), (float)(WF - 1));
    int   w0 = min((int)xw, WF - 2);
    float fw = xw - (float)w0;

    const int lh = h0 - hb;
    const int lw = w0 - wb;
    const float* c00 = &sc[lh][lw][0];
    const float* c01 = &sc[lh][lw+1][0];
    const float* c10 = &sc[lh+1][lw][0];
    const float* c11 = &sc[lh+1][lw+1][0];

    float sA[8], sB[8];
    float best;
    int bestE = -1;                      // -1 => k = 0

    chunk8(c00, c01, c10, c11, 0, fw, fh, sA);
    best = 8.0f * sA[0];                 // exact sample s[0] (scaled)
    scan_head(sA, best, bestE);

    chunk8(c00, c01, c10, c11,  8, fw, fh, sB); scan_mid(sA, sB,  8, best, bestE);
    chunk8(c00, c01, c10, c11, 16, fw, fh, sA); scan_mid(sB, sA, 16, best, bestE);
    chunk8(c00, c01, c10, c11, 24, fw, fh, sB); scan_mid(sA, sB, 24, best, bestE);
    chunk8(c00, c01, c10, c11, 32, fw, fh, sA); scan_mid(sB, sA, 32, best, bestE);
    chunk8(c00, c01, c10, c11, 40, fw, fh, sB); scan_mid(sA, sB, 40, best, bestE);

    {   // e = 47
        float nb = sB[6];
        float cand = fmaf(7.0f, sB[7], nb);
        if (cand > best) { best = cand; bestE = 47; }
    }
    float s47 = sB[7];

    int k;
    if (8.0f * s47 > best) {
        k = 4*(ND-1) + 2;                   // 190: exact sample s[47]
    } else if (bestE < 0) {
        k = 0;
    } else {
        float smL = -3.0e38f, smR = -3.0e38f;
        if (bestE > 0)      smL = bilin1(c00, c01, c10, c11, bestE - 1, fw, fh);
        if (bestE < ND - 1) smR = bilin1(c00, c01, c10, c11, bestE + 1, fw, fh);
        k = 4*bestE + 1 + ((smR > smL) ? 1 : 0);   // tie -> left (smaller k)
    }
    k = max(k, 1);
    pred[ho*WOUT + wo] = (float)k;
}

// ---------------------------------------------------------------------------
extern "C" void kernel_launch(void* const* d_in, const int* in_sizes, int n_in,
                              void* d_out, int out_size)
{
    const float* left  = (const float*)d_in[0];
    const float* right = (const float*)d_in[1];
    float* out = (float*)d_out;

    const int smem_bytes =
        (C*WF + C*TP + WF + WF + WF + TP) * (int)sizeof(float);   // ~54 KB
    cudaFuncSetAttribute(cost_kernel,
                         cudaFuncAttributeMaxDynamicSharedMemorySize, smem_bytes);

    dim3 g1(HF, 3), b1(384);
    cost_kernel<<<g1, b1, smem_bytes>>>(left, right, out);

    dim3 g2(WOUT/32, HOUT/8), b2(32, 8);
    pred_kernel<<<g2, b2>>>(out, out + COST_ELEMS);
}